// round 16
// baseline (speedup 1.0000x reference)
#include <cuda_runtime.h>
#include <cuda_bf16.h>
#include <math.h>
#include <stdint.h>

#define BATCH   2
#define SEQLEN  1024
#define DMODEL  768
#define DINNER  1536
#define DSTATE  64
#define MROWS   (BATCH * SEQLEN)
#define XDBL_LD 132

#define KP1 (3 * DMODEL)             // 2304 (GEMM1 packed K)
#define KPX (3 * DINNER)             // 4608 (x_dbl + GEMM3 packed K)

#define NCH   8                      // scan chunks
#define CHL   (SEQLEN / NCH)         // 128 steps per chunk
#define NPAIR (BATCH * DINNER / 2)   // 1536 channel pairs

// Scratch
__device__ float g_xz   [MROWS * 2 * DINNER];
__device__ float g_xconv[MROWS * DINNER];       // x_dbl split-K partials
__device__ float g_xdbl [MROWS * XDBL_LD];      // col0=dt_in, cols 4..131 = BCBC
__device__ float g_pre  [MROWS * DINNER * 4];   // pre (ch-major) / GEMM3 partials
__device__ float g_cs   [BATCH * DINNER * (NCH - 1) * 128]; // per (ch,chunk): S[64]|P[64]
__device__ __nv_bfloat16 g_xp [MROWS * KP1];
__device__ __nv_bfloat16 g_wip[2 * DINNER * KP1];
__device__ __nv_bfloat16 g_xcp[MROWS * KPX];
__device__ __nv_bfloat16 g_wxp[256 * KPX];
__device__ __nv_bfloat16 g_y2 [MROWS * KPX];
__device__ __nv_bfloat16 g_wop[DMODEL * KPX];

// ---------------------------------------------------------------------------
// Pack bodies + single fused pack_all kernel.
// ---------------------------------------------------------------------------
__device__ __forceinline__ void sp_body(const float* __restrict__ in,
                                        __nv_bfloat16* __restrict__ out,
                                        int i, int K4, int mode)
{
    int K = K4 * 4;
    int row = i / K4;
    int c4  = (i - row * K4) * 4;

    float4 v = *(const float4*)(in + (size_t)row * K + c4);
    float f[4] = {v.x, v.y, v.z, v.w};
    unsigned long long hs[4], ls[4];
#pragma unroll
    for (int t = 0; t < 4; t++) {
        __nv_bfloat16 h = __float2bfloat16_rn(f[t]);
        __nv_bfloat16 l = __float2bfloat16_rn(f[t] - __bfloat162float(h));
        hs[t] = (unsigned long long)__bfloat16_as_ushort(h);
        ls[t] = (unsigned long long)__bfloat16_as_ushort(l);
    }

    if (mode == 3) {
        unsigned long long* wp =
            (unsigned long long*)(out + (size_t)row * 3 * K + 3 * c4);
        wp[0] = hs[0] | (hs[0] << 16) | (ls[0] << 32) | (hs[1] << 48);
        wp[1] = hs[1] | (ls[1] << 16) | (hs[2] << 32) | (hs[2] << 48);
        wp[2] = ls[2] | (hs[3] << 16) | (hs[3] << 32) | (ls[3] << 48);
    } else {
        unsigned h0 = (unsigned)hs[0] | ((unsigned)hs[1] << 16);
        unsigned h1 = (unsigned)hs[2] | ((unsigned)hs[3] << 16);
        unsigned l0 = (unsigned)ls[0] | ((unsigned)ls[1] << 16);
        unsigned l1 = (unsigned)ls[2] | ((unsigned)ls[3] << 16);
        uint2 hi = make_uint2(h0, h1);
        uint2 lo = make_uint2(l0, l1);
        __nv_bfloat16* base = out + (size_t)row * 3 * K + c4;
        *(uint2*)(base)         = hi;
        *(uint2*)(base + K)     = mode ? hi : lo;
        *(uint2*)(base + 2 * K) = mode ? lo : hi;
    }
}

__device__ __forceinline__ void wx_body(const float* __restrict__ Wx,
                                        __nv_bfloat16* __restrict__ out, int i)
{
    const int K4 = DINNER / 4;
    int r = i / K4;
    int c4 = (i - r * K4) * 4;

    int s = -1;
    if (r == 0) s = 0;
    else if (r >= 4 && r < 132) {
        int g = (r - 4) >> 2, j = (r - 4) & 3;
        s = (j < 2) ? (1 + 2 * g + j) : (65 + 2 * g + (j - 2));
    }

    float f[4] = {0.f, 0.f, 0.f, 0.f};
    if (s >= 0) {
        float4 v = *(const float4*)(Wx + (size_t)s * DINNER + c4);
        f[0] = v.x; f[1] = v.y; f[2] = v.z; f[3] = v.w;
    }
    unsigned hs[4], ls[4];
#pragma unroll
    for (int t = 0; t < 4; t++) {
        __nv_bfloat16 h = __float2bfloat16_rn(f[t]);
        __nv_bfloat16 l = __float2bfloat16_rn(f[t] - __bfloat162float(h));
        hs[t] = (unsigned)__bfloat16_as_ushort(h);
        ls[t] = (unsigned)__bfloat16_as_ushort(l);
    }
    uint2 hi = make_uint2(hs[0] | (hs[1] << 16), hs[2] | (hs[3] << 16));
    uint2 lo = make_uint2(ls[0] | (ls[1] << 16), ls[2] | (ls[3] << 16));
    __nv_bfloat16* base = out + (size_t)r * KPX + c4;
    *(uint2*)(base)              = hi;
    *(uint2*)(base + DINNER)     = hi;
    *(uint2*)(base + 2 * DINNER) = lo;
}

#define T_X  (MROWS * DMODEL / 4)
#define T_WI (2 * DINNER * DMODEL / 4)
#define T_WO (DMODEL * DINNER / 4)
#define T_WX (256 * (DINNER / 4))
#define T_ALL (T_X + T_WI + T_WO + T_WX)

__global__ void pack_all(const float* __restrict__ x,
                         const float* __restrict__ W_in,
                         const float* __restrict__ W_out,
                         const float* __restrict__ W_x)
{
    int i = blockIdx.x * blockDim.x + threadIdx.x;
    if (i < T_X) {
        sp_body(x, g_xp, i, DMODEL / 4, 0);
    } else if (i < T_X + T_WI) {
        sp_body(W_in, g_wip, i - T_X, DMODEL / 4, 1);
    } else if (i < T_X + T_WI + T_WO) {
        sp_body(W_out, g_wop, i - T_X - T_WI, DINNER / 4, 3);
    } else if (i < T_ALL) {
        wx_body(W_x, g_wxp, i - T_X - T_WI - T_WO);
    }
}

// ---------------------------------------------------------------------------
// 3-stage pipelined bf16 mma.sync GEMM, 128x128x32, launch_bounds(256,2).
// ---------------------------------------------------------------------------
__device__ __forceinline__ void mma16816(float* c, const unsigned* a,
                                         const unsigned* b)
{
    asm volatile(
        "mma.sync.aligned.m16n8k16.row.col.f32.bf16.bf16.f32 "
        "{%0,%1,%2,%3}, {%4,%5,%6,%7}, {%8,%9}, {%0,%1,%2,%3};\n"
        : "+f"(c[0]), "+f"(c[1]), "+f"(c[2]), "+f"(c[3])
        : "r"(a[0]), "r"(a[1]), "r"(a[2]), "r"(a[3]),
          "r"(b[0]), "r"(b[1]));
}
__device__ __forceinline__ void ldsm4(unsigned& r0, unsigned& r1,
                                      unsigned& r2, unsigned& r3,
                                      const void* p)
{
    unsigned a = (unsigned)__cvta_generic_to_shared(p);
    asm volatile("ldmatrix.sync.aligned.m8n8.x4.shared.b16 {%0,%1,%2,%3}, [%4];"
                 : "=r"(r0), "=r"(r1), "=r"(r2), "=r"(r3) : "r"(a));
}
__device__ __forceinline__ void cp16(void* smem, const void* gmem)
{
    unsigned s = (unsigned)__cvta_generic_to_shared(smem);
    asm volatile("cp.async.cg.shared.global [%0], [%1], 16;" :: "r"(s), "l"(gmem));
}

#define NSTAGE 3

__global__ __launch_bounds__(256, 2) void gemm_bf16p(
    const __nv_bfloat16* __restrict__ A, const __nv_bfloat16* __restrict__ B,
    float* __restrict__ C, int M, int ldN, int K, int kLen, int Nc)
{
    constexpr int BM = 128, BN = 128, BK = 32;
    constexpr int MT = 4, NT = 4;

    __shared__ __nv_bfloat16 As[NSTAGE][BM][40];
    __shared__ __nv_bfloat16 Bs[NSTAGE][BN][40];

    const int tid  = threadIdx.x;
    const int lane = tid & 31;
    const int wid  = tid >> 5;
    const int wm   = wid & 1;
    const int wn   = wid >> 1;
    const int bm   = blockIdx.y * BM;
    const int bn   = blockIdx.x * BN;
    const int kBase = blockIdx.z * kLen;
    float* Cz = C + (size_t)blockIdx.z * M * ldN;

    const int srow = tid >> 2;
    const int sseg = tid & 3;
    const __nv_bfloat16* Ag = A + (size_t)(bm + srow) * K + kBase + sseg * 8;
    const __nv_bfloat16* Bg = B + (size_t)(bn + srow) * K + kBase + sseg * 8;

    float c[MT][NT][4];
#pragma unroll
    for (int i = 0; i < MT; i++)
#pragma unroll
        for (int j = 0; j < NT; j++)
#pragma unroll
            for (int r = 0; r < 4; r++) c[i][j][r] = 0.f;

    auto load_stage = [&](int s, int k0) {
        cp16(&As[s][srow][sseg * 8],      Ag + k0);
        cp16(&As[s][srow + 64][sseg * 8], Ag + (size_t)64 * K + k0);
        cp16(&Bs[s][srow][sseg * 8],      Bg + k0);
        cp16(&Bs[s][srow + 64][sseg * 8], Bg + (size_t)64 * K + k0);
    };

    auto compute_half = [&](int s, int ks) {
        unsigned a[MT][4], b[NT][2];
#pragma unroll
        for (int i = 0; i < MT; i++)
            ldsm4(a[i][0], a[i][1], a[i][2], a[i][3],
                  &As[s][wm * 64 + i * 16 + (lane & 15)]
                       [ks * 16 + ((lane >> 4) << 3)]);
#pragma unroll
        for (int j2 = 0; j2 < NT / 2; j2++) {
            int r = wn * 32 + j2 * 16 + ((lane >> 4) << 3) + (lane & 7);
            int cb = (((lane >> 3) & 1) << 3) + ks * 16;
            ldsm4(b[2 * j2][0], b[2 * j2][1], b[2 * j2 + 1][0], b[2 * j2 + 1][1],
                  &Bs[s][r][cb]);
        }
#pragma unroll
        for (int i = 0; i < MT; i++)
#pragma unroll
            for (int j = 0; j < NT; j++)
                mma16816(c[i][j], a[i], b[j]);
    };

    const int nIter = kLen / BK;

    load_stage(0, 0);
    asm volatile("cp.async.commit_group;");
    if (1 < nIter) load_stage(1, BK);
    asm volatile("cp.async.commit_group;");
    asm volatile("cp.async.wait_group 1;");
    __syncthreads();

    int s = 0;
    for (int it = 0; it < nIter; it++) {
        compute_half(s, 0);
        {
            int nf = it + 2;
            int sl = s + 2; if (sl >= NSTAGE) sl -= NSTAGE;
            if (nf < nIter) load_stage(sl, nf * BK);
            asm volatile("cp.async.commit_group;");
        }
        compute_half(s, 1);
        asm volatile("cp.async.wait_group 1;");
        __syncthreads();
        s = (s + 1 == NSTAGE) ? 0 : s + 1;
    }

#pragma unroll
    for (int i = 0; i < MT; i++) {
        int row = bm + wm * 64 + i * 16 + (lane >> 2);
#pragma unroll
        for (int j = 0; j < NT; j++) {
            int col = bn + wn * 32 + j * 8 + (lane & 3) * 2;
            if (col < Nc) {
                *(float2*)(Cz + (size_t)row * ldN + col) =
                    make_float2(c[i][j][0], c[i][j][1]);
                *(float2*)(Cz + (size_t)(row + 8) * ldN + col) =
                    make_float2(c[i][j][2], c[i][j][3]);
            }
        }
    }
}

// Split-K reduction
__global__ void addk_kernel(const float* __restrict__ p, float* __restrict__ out,
                            int total4, int ns)
{
    int i = blockIdx.x * blockDim.x + threadIdx.x;
    if (i >= total4) return;
    float4 a = ((const float4*)p)[i];
    for (int s = 1; s < ns; s++) {
        float4 b = ((const float4*)p)[i + (size_t)s * total4];
        a.x += b.x; a.y += b.y; a.z += b.z; a.w += b.w;
    }
    ((float4*)out)[i] = a;
}

// ---------------------------------------------------------------------------
// Causal conv (width 4) + SiLU, fused with bf16 split-pack -> g_xcp
// ---------------------------------------------------------------------------
__global__ void conv_silu_pack(const float* __restrict__ cw,
                               const float* __restrict__ cb)
{
    int i = blockIdx.x * blockDim.x + threadIdx.x;
    const int ngrp = DINNER / 4;
    if (i >= MROWS * ngrp) return;
    int m  = i / ngrp;
    int dg = i % ngrp;
    int l  = m % SEQLEN;
    int d0 = dg * 4;

    float4 acc = make_float4(cb[d0], cb[d0 + 1], cb[d0 + 2], cb[d0 + 3]);
#pragma unroll
    for (int t = 0; t < 4; t++) {
        int li = l - 3 + t;
        if (li >= 0) {
            const float4 v = *(const float4*)&g_xz[(size_t)(m - l + li) * (2 * DINNER) + d0];
            acc.x = fmaf(v.x, __ldg(&cw[(d0 + 0) * 4 + t]), acc.x);
            acc.y = fmaf(v.y, __ldg(&cw[(d0 + 1) * 4 + t]), acc.y);
            acc.z = fmaf(v.z, __ldg(&cw[(d0 + 2) * 4 + t]), acc.z);
            acc.w = fmaf(v.w, __ldg(&cw[(d0 + 3) * 4 + t]), acc.w);
        }
    }
    float f[4];
    f[0] = acc.x / (1.f + expf(-acc.x));
    f[1] = acc.y / (1.f + expf(-acc.y));
    f[2] = acc.z / (1.f + expf(-acc.z));
    f[3] = acc.w / (1.f + expf(-acc.w));

    unsigned long long hs[4], ls[4];
#pragma unroll
    for (int t = 0; t < 4; t++) {
        __nv_bfloat16 h = __float2bfloat16_rn(f[t]);
        __nv_bfloat16 lo = __float2bfloat16_rn(f[t] - __bfloat162float(h));
        hs[t] = (unsigned long long)__bfloat16_as_ushort(h);
        ls[t] = (unsigned long long)__bfloat16_as_ushort(lo);
    }
    unsigned long long hp = hs[0] | (hs[1] << 16) | (hs[2] << 32) | (hs[3] << 48);
    unsigned long long lp = ls[0] | (ls[1] << 16) | (ls[2] << 32) | (ls[3] << 48);
    __nv_bfloat16* base = g_xcp + (size_t)m * KPX + d0;
    *(unsigned long long*)(base)              = hp;
    *(unsigned long long*)(base + DINNER)     = lp;
    *(unsigned long long*)(base + 2 * DINNER) = hp;
}

// ---------------------------------------------------------------------------
// Pre: {dt, dt*xc, D*xc*sz, sz} -> channel-major [ch][l] via smem transpose.
// ---------------------------------------------------------------------------
__global__ __launch_bounds__(256) void pre_kernel_tile(
    const float* __restrict__ dt_w, const float* __restrict__ dt_b,
    const float* __restrict__ Dp)
{
    __shared__ float sA[32][65], sB[32][65], sC[32][65], sD[32][65];

    const int NCT = BATCH * DINNER / 32;
    const int tid = threadIdx.x;
    const int tc  = blockIdx.x % NCT;
    const int tl  = blockIdx.x / NCT;
    const int ch0 = tc * 32;
    const int l0  = tl * 64;
    const int b   = ch0 / DINNER;

    const int dof = tid & 31;
    const int d   = (ch0 % DINNER) + dof;
    const int wl  = tid >> 5;

    const float dw = __ldg(dt_w + d), db = __ldg(dt_b + d), Dv = __ldg(Dp + d);

#pragma unroll
    for (int p = 0; p < 8; p++) {
        int le = wl + p * 8;
        int m = b * SEQLEN + l0 + le;
        float dtin = g_xdbl[(size_t)m * XDBL_LD];
        float xarg = fmaf(dtin, dw, db);
        float dt = fmaxf(xarg, 0.f) + log1pf(expf(-fabsf(xarg)));
        float xc = __bfloat162float(g_xcp[(size_t)m * KPX + d]) +
                   __bfloat162float(g_xcp[(size_t)m * KPX + DINNER + d]);
        float z  = g_xz[(size_t)m * (2 * DINNER) + DINNER + d];
        float sz = z / (1.f + expf(-z));
        sA[dof][le] = dt;
        sB[dof][le] = dt * xc;
        sC[dof][le] = Dv * xc * sz;
        sD[dof][le] = sz;
    }
    __syncthreads();

    const int cl = tid >> 3;
    const int j  = tid & 7;
    float4* outp = (float4*)g_pre + (size_t)(ch0 + cl) * SEQLEN + l0;
#pragma unroll
    for (int k = 0; k < 8; k++) {
        int e = k * 8 + j;
        outp[e] = make_float4(sA[cl][e], sB[cl][e], sC[cl][e], sD[cl][e]);
    }
}

// ---------------------------------------------------------------------------
// Chunked selective scan, 2 channels per warp.
// Pass 1: per (pair, chunk 0..6) compute chunk-final state S and decay P
//         (h0 = 0 within chunk; P[n] = exp2(An * sum dt), exact product).
// Pass 2: per (pair, chunk 0..7) combine prefix (S,P), then full scan body.
// g_cs layout per (ch, chunk): 128 floats = S[64] | P[64].
// ---------------------------------------------------------------------------
__device__ __forceinline__ float fast_ex2(float x) {
    float r;
    asm("ex2.approx.ftz.f32 %0, %1;" : "=f"(r) : "f"(x));
    return r;
}

__global__ __launch_bounds__(256) void scan_state(const float* __restrict__ A_log)
{
    const int gw   = blockIdx.x * 8 + (threadIdx.x >> 5);
    const int lane = threadIdx.x & 31;
    const int pair  = gw % NPAIR;
    const int chunk = gw / NPAIR;          // 0..6
    const int b  = pair / (DINNER / 2);
    const int d0 = (pair % (DINNER / 2)) * 2;
    const int chA = b * DINNER + d0;
    const int n0 = 2 * lane;

    const float LOG2E = 1.4426950408889634f;
    const float An0 = -expf(A_log[n0])     * LOG2E;
    const float An1 = -expf(A_log[n0 + 1]) * LOG2E;

    const int l0 = chunk * CHL;
    const float4* prA = (const float4*)g_pre + (size_t)chA * SEQLEN + l0;
    const float4* prB = prA + SEQLEN;
    const float*  xb  = g_xdbl + (size_t)(b * SEQLEN + l0) * XDBL_LD;

    float4 pA[4], pB[4]; float2 Bv[4];
#pragma unroll
    for (int s = 0; s < 4; s++) {
        pA[s] = __ldg(prA + s);
        pB[s] = __ldg(prB + s);
        Bv[s] = __ldg((const float2*)(xb + (size_t)s * XDBL_LD + 4 + 2 * n0));
    }

    float hA0 = 0.f, hA1 = 0.f, hB0 = 0.f, hB1 = 0.f;
    float sdA = 0.f, sdB = 0.f;

    for (int l = 0; l < CHL; l += 4) {
#pragma unroll
        for (int s = 0; s < 4; s++) {
            float4 a = pA[s], q = pB[s]; float2 c = Bv[s];
            float dA0 = fast_ex2(a.x * An0);
            float dA1 = fast_ex2(a.x * An1);
            hA0 = fmaf(hA0, dA0, c.x * a.y);
            hA1 = fmaf(hA1, dA1, c.y * a.y);
            sdA += a.x;
            float eB0 = fast_ex2(q.x * An0);
            float eB1 = fast_ex2(q.x * An1);
            hB0 = fmaf(hB0, eB0, c.x * q.y);
            hB1 = fmaf(hB1, eB1, c.y * q.y);
            sdB += q.x;
            int ln = l + 4 + s;
            if (ln > CHL - 1) ln = CHL - 1;
            pA[s] = __ldg(prA + ln);
            pB[s] = __ldg(prB + ln);
            Bv[s] = __ldg((const float2*)(xb + (size_t)ln * XDBL_LD + 4 + 2 * n0));
        }
    }

    float2* csA = (float2*)(g_cs + ((size_t)chA * (NCH - 1) + chunk) * 128);
    float2* csB = (float2*)(g_cs + ((size_t)(chA + 1) * (NCH - 1) + chunk) * 128);
    csA[lane]      = make_float2(hA0, hA1);
    csA[32 + lane] = make_float2(fast_ex2(An0 * sdA), fast_ex2(An1 * sdA));
    csB[lane]      = make_float2(hB0, hB1);
    csB[32 + lane] = make_float2(fast_ex2(An0 * sdB), fast_ex2(An1 * sdB));
}

__global__ __launch_bounds__(256) void scan_main(const float* __restrict__ A_log)
{
    const int gw   = blockIdx.x * 8 + (threadIdx.x >> 5);
    const int lane = threadIdx.x & 31;
    const int pair  = gw % NPAIR;
    const int chunk = gw / NPAIR;          // 0..7
    const int b  = pair / (DINNER / 2);
    const int d0 = (pair % (DINNER / 2)) * 2;
    const int chA = b * DINNER + d0;
    const int n0 = 2 * lane;

    const float LOG2E = 1.4426950408889634f;
    const float An0 = -expf(A_log[n0])     * LOG2E;
    const float An1 = -expf(A_log[n0 + 1]) * LOG2E;

    const int l0 = chunk * CHL;
    const float4* prA = (const float4*)g_pre + (size_t)chA * SEQLEN + l0;
    const float4* prB = prA + SEQLEN;
    const float*  xb  = g_xdbl + (size_t)(b * SEQLEN + l0) * XDBL_LD;
    __nv_bfloat16* yoA = g_y2 + (size_t)(b * SEQLEN + l0) * KPX + 3 * d0;
    __nv_bfloat16* yoB = yoA + 3;

    // h_in = fold of (h*P + S) over prefix chunks
    float hA0 = 0.f, hA1 = 0.f, hB0 = 0.f, hB1 = 0.f;
    for (int j = 0; j < chunk; j++) {
        const float2* csA = (const float2*)(g_cs + ((size_t)chA * (NCH - 1) + j) * 128);
        const float2* csB = (const float2*)(g_cs + ((size_t)(chA + 1) * (NCH - 1) + j) * 128);
        float2 S = csA[lane], P = csA[32 + lane];
        hA0 = fmaf(hA0, P.x, S.x);
        hA1 = fmaf(hA1, P.y, S.y);
        float2 Sb = csB[lane], Pb = csB[32 + lane];
        hB0 = fmaf(hB0, Pb.x, Sb.x);
        hB1 = fmaf(hB1, Pb.y, Sb.y);
    }

    float4 pA[4], pB[4], bc[4];
#pragma unroll
    for (int s = 0; s < 4; s++) {
        pA[s] = __ldg(prA + s);
        pB[s] = __ldg(prB + s);
        bc[s] = __ldg((const float4*)(xb + (size_t)s * XDBL_LD + 4 + 2 * n0));
    }

    const bool u16 = (lane & 16) != 0;
    const bool u8  = (lane & 8) != 0;
    const bool u4  = (lane & 4) != 0;

    for (int l = 0; l < CHL; l += 4) {
        float yA[4], yB[4], zA[4], zB[4], wA[4], wB[4];
#pragma unroll
        for (int s = 0; s < 4; s++) {
            float4 a = pA[s], q = pB[s], c = bc[s];
            float dA0 = fast_ex2(a.x * An0);
            float dA1 = fast_ex2(a.x * An1);
            hA0 = fmaf(hA0, dA0, c.x * a.y);
            hA1 = fmaf(hA1, dA1, c.y * a.y);
            yA[s] = fmaf(hA0, c.z, hA1 * c.w);
            zA[s] = a.z; wA[s] = a.w;
            float eB0 = fast_ex2(q.x * An0);
            float eB1 = fast_ex2(q.x * An1);
            hB0 = fmaf(hB0, eB0, c.x * q.y);
            hB1 = fmaf(hB1, eB1, c.y * q.y);
            yB[s] = fmaf(hB0, c.z, hB1 * c.w);
            zB[s] = q.z; wB[s] = q.w;
            int ln = l + 4 + s;
            if (ln > CHL - 1) ln = CHL - 1;
            pA[s] = __ldg(prA + ln);
            pB[s] = __ldg(prB + ln);
            bc[s] = __ldg((const float4*)(xb + (size_t)ln * XDBL_LD + 4 + 2 * n0));
        }

        float v[4], z[4], w[4];
#pragma unroll
        for (int s = 0; s < 4; s++) {
            float send = u16 ? yA[s] : yB[s];
            float recv = __shfl_xor_sync(0xffffffffu, send, 16);
            v[s] = (u16 ? yB[s] : yA[s]) + recv;
            z[s] = u16 ? zB[s] : zA[s];
            w[s] = u16 ? wB[s] : wA[s];
        }
#pragma unroll
        for (int s = 0; s < 2; s++) {
            float send = u8 ? v[s] : v[s + 2];
            float recv = __shfl_xor_sync(0xffffffffu, send, 8);
            v[s] = (u8 ? v[s + 2] : v[s]) + recv;
            z[s] = u8 ? z[s + 2] : z[s];
            w[s] = u8 ? w[s + 2] : w[s];
        }
        {
            float send = u4 ? v[0] : v[1];
            float recv = __shfl_xor_sync(0xffffffffu, send, 4);
            v[0] = (u4 ? v[1] : v[0]) + recv;
            z[0] = u4 ? z[1] : z[0];
            w[0] = u4 ? w[1] : w[0];
        }
        v[0] += __shfl_xor_sync(0xffffffffu, v[0], 2);
        v[0] += __shfl_xor_sync(0xffffffffu, v[0], 1);

        if ((lane & 3) == 0) {
            int slot = lane >> 2;           // 0..7: 0-3 = chA steps, 4-7 = chB
            float yv = fmaf(v[0], w[0], z[0]);
            __nv_bfloat16 hi = __float2bfloat16_rn(yv);
            __nv_bfloat16 lo = __float2bfloat16_rn(yv - __bfloat162float(hi));
            __nv_bfloat16* p = (slot < 4)
                ? yoA + (size_t)(l + slot) * KPX
                : yoB + (size_t)(l + slot - 4) * KPX;
            p[0] = hi; p[1] = lo; p[2] = hi;
        }
    }
}

// ---------------------------------------------------------------------------
extern "C" void kernel_launch(void* const* d_in, const int* in_sizes, int n_in,
                              void* d_out, int out_size)
{
    const float* x      = (const float*)d_in[0];
    const float* W_in   = (const float*)d_in[1];
    const float* conv_w = (const float*)d_in[2];
    const float* conv_b = (const float*)d_in[3];
    const float* W_x    = (const float*)d_in[4];
    const float* dt_w   = (const float*)d_in[5];
    const float* dt_b   = (const float*)d_in[6];
    const float* A_log  = (const float*)d_in[7];
    const float* D_par  = (const float*)d_in[8];
    const float* W_out  = (const float*)d_in[9];
    float* out = (float*)d_out;

    float *p_xz, *p_xdbl, *p_part, *p_pre;
    __nv_bfloat16 *p_xp, *p_wip, *p_xcp, *p_wxp, *p_y2, *p_wop;
    cudaGetSymbolAddress((void**)&p_xz,   g_xz);
    cudaGetSymbolAddress((void**)&p_xdbl, g_xdbl);
    cudaGetSymbolAddress((void**)&p_part, g_xconv);
    cudaGetSymbolAddress((void**)&p_pre,  g_pre);
    cudaGetSymbolAddress((void**)&p_xp,   g_xp);
    cudaGetSymbolAddress((void**)&p_wip,  g_wip);
    cudaGetSymbolAddress((void**)&p_xcp,  g_xcp);
    cudaGetSymbolAddress((void**)&p_wxp,  g_wxp);
    cudaGetSymbolAddress((void**)&p_y2,   g_y2);
    cudaGetSymbolAddress((void**)&p_wop,  g_wop);

    // 1) fused input packs (x, W_in, W_out, W_x)
    pack_all<<<(T_ALL + 255) / 256, 256>>>(x, W_in, W_out, W_x);

    // 2) xz = x @ W_in^T
    gemm_bf16p<<<dim3(2 * DINNER / 128, MROWS / 128, 1), 256>>>(
        p_xp, p_wip, p_xz, MROWS, 2 * DINNER, KP1, KP1, 2 * DINNER);

    // 3) causal conv + silu + pack
    {
        int total = MROWS * (DINNER / 4);
        conv_silu_pack<<<(total + 255) / 256, 256>>>(conv_w, conv_b);
    }

    // 4) x_dbl = x_conv @ W_x~^T (BC-interleaved output cols, splitK=8)
    gemm_bf16p<<<dim3(2, MROWS / 128, 8), 256>>>(
        p_xcp, p_wxp, p_part, MROWS, XDBL_LD, KPX, KPX / 8, XDBL_LD);
    {
        int t4 = MROWS * XDBL_LD / 4;
        addk_kernel<<<(t4 + 255) / 256, 256>>>(p_part, p_xdbl, t4, 8);
    }

    // 5) pre (channel-major via smem transpose)
    pre_kernel_tile<<<(BATCH * DINNER / 32) * (SEQLEN / 64), 256>>>(
        dt_w, dt_b, D_par);

    // 6) chunked selective scan -> g_y2
    scan_state<<<NPAIR * (NCH - 1) / 8, 256>>>(A_log);
    scan_main<<<NPAIR * NCH / 8, 256>>>(A_log);

    // 7) out = y @ W_out^T (K=4608, splitK=4 in g_pre -> add)
    gemm_bf16p<<<dim3(DMODEL / 128, MROWS / 128, 4), 256>>>(
        p_y2, p_wop, p_pre, MROWS, DMODEL, KPX, KPX / 4, DMODEL);
    {
        int t4 = MROWS * DMODEL / 4;
        addk_kernel<<<(t4 + 255) / 256, 256>>>(p_pre, out, t4, 4);
    }
}

// round 17
// speedup vs baseline: 1.0722x; 1.0722x over previous
#include <cuda_runtime.h>
#include <cuda_bf16.h>
#include <math.h>
#include <stdint.h>

#define BATCH   2
#define SEQLEN  1024
#define DMODEL  768
#define DINNER  1536
#define DSTATE  64
#define MROWS   (BATCH * SEQLEN)
#define XDBL_LD 132

#define KP1 (3 * DMODEL)             // 2304 (GEMM1 packed K)
#define KPX (3 * DINNER)             // 4608 (x_dbl + GEMM3 packed K)

#define NCH   4                      // scan chunks
#define CHL   (SEQLEN / NCH)         // 256 steps per chunk
#define NPAIR (BATCH * DINNER / 2)   // 1536 channel pairs

// Scratch
__device__ float g_xz   [MROWS * 2 * DINNER];
__device__ float g_xconv[MROWS * DINNER];       // x_dbl split-K partials
__device__ float g_xdbl [MROWS * XDBL_LD];      // col0=dt_in, cols 4..131 = BCBC
__device__ float g_pre  [MROWS * DINNER * 4];   // GEMM3 split-K partials
__device__ float g_pre2 [MROWS * DINNER * 2];   // {dt, dt*xc} ch-major [ch][l]
__device__ float g_zw   [MROWS * DINNER * 2];   // {D*xc*sz, sz} ch-major [ch][l]
__device__ float g_cs   [BATCH * DINNER * (NCH - 1) * 128]; // (ch,chunk): S[64]|P[64]
__device__ __nv_bfloat16 g_xp [MROWS * KP1];
__device__ __nv_bfloat16 g_wip[2 * DINNER * KP1];
__device__ __nv_bfloat16 g_xcp[MROWS * KPX];
__device__ __nv_bfloat16 g_wxp[256 * KPX];
__device__ __nv_bfloat16 g_y2 [MROWS * KPX];
__device__ __nv_bfloat16 g_wop[DMODEL * KPX];

// ---------------------------------------------------------------------------
// Pack bodies + single fused pack_all kernel.
// ---------------------------------------------------------------------------
__device__ __forceinline__ void sp_body(const float* __restrict__ in,
                                        __nv_bfloat16* __restrict__ out,
                                        int i, int K4, int mode)
{
    int K = K4 * 4;
    int row = i / K4;
    int c4  = (i - row * K4) * 4;

    float4 v = *(const float4*)(in + (size_t)row * K + c4);
    float f[4] = {v.x, v.y, v.z, v.w};
    unsigned long long hs[4], ls[4];
#pragma unroll
    for (int t = 0; t < 4; t++) {
        __nv_bfloat16 h = __float2bfloat16_rn(f[t]);
        __nv_bfloat16 l = __float2bfloat16_rn(f[t] - __bfloat162float(h));
        hs[t] = (unsigned long long)__bfloat16_as_ushort(h);
        ls[t] = (unsigned long long)__bfloat16_as_ushort(l);
    }

    if (mode == 3) {
        unsigned long long* wp =
            (unsigned long long*)(out + (size_t)row * 3 * K + 3 * c4);
        wp[0] = hs[0] | (hs[0] << 16) | (ls[0] << 32) | (hs[1] << 48);
        wp[1] = hs[1] | (ls[1] << 16) | (hs[2] << 32) | (hs[2] << 48);
        wp[2] = ls[2] | (hs[3] << 16) | (hs[3] << 32) | (ls[3] << 48);
    } else {
        unsigned h0 = (unsigned)hs[0] | ((unsigned)hs[1] << 16);
        unsigned h1 = (unsigned)hs[2] | ((unsigned)hs[3] << 16);
        unsigned l0 = (unsigned)ls[0] | ((unsigned)ls[1] << 16);
        unsigned l1 = (unsigned)ls[2] | ((unsigned)ls[3] << 16);
        uint2 hi = make_uint2(h0, h1);
        uint2 lo = make_uint2(l0, l1);
        __nv_bfloat16* base = out + (size_t)row * 3 * K + c4;
        *(uint2*)(base)         = hi;
        *(uint2*)(base + K)     = mode ? hi : lo;
        *(uint2*)(base + 2 * K) = mode ? lo : hi;
    }
}

__device__ __forceinline__ void wx_body(const float* __restrict__ Wx,
                                        __nv_bfloat16* __restrict__ out, int i)
{
    const int K4 = DINNER / 4;
    int r = i / K4;
    int c4 = (i - r * K4) * 4;

    int s = -1;
    if (r == 0) s = 0;
    else if (r >= 4 && r < 132) {
        int g = (r - 4) >> 2, j = (r - 4) & 3;
        s = (j < 2) ? (1 + 2 * g + j) : (65 + 2 * g + (j - 2));
    }

    float f[4] = {0.f, 0.f, 0.f, 0.f};
    if (s >= 0) {
        float4 v = *(const float4*)(Wx + (size_t)s * DINNER + c4);
        f[0] = v.x; f[1] = v.y; f[2] = v.z; f[3] = v.w;
    }
    unsigned hs[4], ls[4];
#pragma unroll
    for (int t = 0; t < 4; t++) {
        __nv_bfloat16 h = __float2bfloat16_rn(f[t]);
        __nv_bfloat16 l = __float2bfloat16_rn(f[t] - __bfloat162float(h));
        hs[t] = (unsigned)__bfloat16_as_ushort(h);
        ls[t] = (unsigned)__bfloat16_as_ushort(l);
    }
    uint2 hi = make_uint2(hs[0] | (hs[1] << 16), hs[2] | (hs[3] << 16));
    uint2 lo = make_uint2(ls[0] | (ls[1] << 16), ls[2] | (ls[3] << 16));
    __nv_bfloat16* base = out + (size_t)r * KPX + c4;
    *(uint2*)(base)              = hi;
    *(uint2*)(base + DINNER)     = hi;
    *(uint2*)(base + 2 * DINNER) = lo;
}

#define T_X  (MROWS * DMODEL / 4)
#define T_WI (2 * DINNER * DMODEL / 4)
#define T_WO (DMODEL * DINNER / 4)
#define T_WX (256 * (DINNER / 4))
#define T_ALL (T_X + T_WI + T_WO + T_WX)

__global__ void pack_all(const float* __restrict__ x,
                         const float* __restrict__ W_in,
                         const float* __restrict__ W_out,
                         const float* __restrict__ W_x)
{
    int i = blockIdx.x * blockDim.x + threadIdx.x;
    if (i < T_X) {
        sp_body(x, g_xp, i, DMODEL / 4, 0);
    } else if (i < T_X + T_WI) {
        sp_body(W_in, g_wip, i - T_X, DMODEL / 4, 1);
    } else if (i < T_X + T_WI + T_WO) {
        sp_body(W_out, g_wop, i - T_X - T_WI, DINNER / 4, 3);
    } else if (i < T_ALL) {
        wx_body(W_x, g_wxp, i - T_X - T_WI - T_WO);
    }
}

// ---------------------------------------------------------------------------
// 3-stage pipelined bf16 mma.sync GEMM, 128x128x32, launch_bounds(256,2).
// ---------------------------------------------------------------------------
__device__ __forceinline__ void mma16816(float* c, const unsigned* a,
                                         const unsigned* b)
{
    asm volatile(
        "mma.sync.aligned.m16n8k16.row.col.f32.bf16.bf16.f32 "
        "{%0,%1,%2,%3}, {%4,%5,%6,%7}, {%8,%9}, {%0,%1,%2,%3};\n"
        : "+f"(c[0]), "+f"(c[1]), "+f"(c[2]), "+f"(c[3])
        : "r"(a[0]), "r"(a[1]), "r"(a[2]), "r"(a[3]),
          "r"(b[0]), "r"(b[1]));
}
__device__ __forceinline__ void ldsm4(unsigned& r0, unsigned& r1,
                                      unsigned& r2, unsigned& r3,
                                      const void* p)
{
    unsigned a = (unsigned)__cvta_generic_to_shared(p);
    asm volatile("ldmatrix.sync.aligned.m8n8.x4.shared.b16 {%0,%1,%2,%3}, [%4];"
                 : "=r"(r0), "=r"(r1), "=r"(r2), "=r"(r3) : "r"(a));
}
__device__ __forceinline__ void cp16(void* smem, const void* gmem)
{
    unsigned s = (unsigned)__cvta_generic_to_shared(smem);
    asm volatile("cp.async.cg.shared.global [%0], [%1], 16;" :: "r"(s), "l"(gmem));
}

#define NSTAGE 3

__global__ __launch_bounds__(256, 2) void gemm_bf16p(
    const __nv_bfloat16* __restrict__ A, const __nv_bfloat16* __restrict__ B,
    float* __restrict__ C, int M, int ldN, int K, int kLen, int Nc)
{
    constexpr int BM = 128, BN = 128, BK = 32;
    constexpr int MT = 4, NT = 4;

    __shared__ __nv_bfloat16 As[NSTAGE][BM][40];
    __shared__ __nv_bfloat16 Bs[NSTAGE][BN][40];

    const int tid  = threadIdx.x;
    const int lane = tid & 31;
    const int wid  = tid >> 5;
    const int wm   = wid & 1;
    const int wn   = wid >> 1;
    const int bm   = blockIdx.y * BM;
    const int bn   = blockIdx.x * BN;
    const int kBase = blockIdx.z * kLen;
    float* Cz = C + (size_t)blockIdx.z * M * ldN;

    const int srow = tid >> 2;
    const int sseg = tid & 3;
    const __nv_bfloat16* Ag = A + (size_t)(bm + srow) * K + kBase + sseg * 8;
    const __nv_bfloat16* Bg = B + (size_t)(bn + srow) * K + kBase + sseg * 8;

    float c[MT][NT][4];
#pragma unroll
    for (int i = 0; i < MT; i++)
#pragma unroll
        for (int j = 0; j < NT; j++)
#pragma unroll
            for (int r = 0; r < 4; r++) c[i][j][r] = 0.f;

    auto load_stage = [&](int s, int k0) {
        cp16(&As[s][srow][sseg * 8],      Ag + k0);
        cp16(&As[s][srow + 64][sseg * 8], Ag + (size_t)64 * K + k0);
        cp16(&Bs[s][srow][sseg * 8],      Bg + k0);
        cp16(&Bs[s][srow + 64][sseg * 8], Bg + (size_t)64 * K + k0);
    };

    auto compute_half = [&](int s, int ks) {
        unsigned a[MT][4], b[NT][2];
#pragma unroll
        for (int i = 0; i < MT; i++)
            ldsm4(a[i][0], a[i][1], a[i][2], a[i][3],
                  &As[s][wm * 64 + i * 16 + (lane & 15)]
                       [ks * 16 + ((lane >> 4) << 3)]);
#pragma unroll
        for (int j2 = 0; j2 < NT / 2; j2++) {
            int r = wn * 32 + j2 * 16 + ((lane >> 4) << 3) + (lane & 7);
            int cb = (((lane >> 3) & 1) << 3) + ks * 16;
            ldsm4(b[2 * j2][0], b[2 * j2][1], b[2 * j2 + 1][0], b[2 * j2 + 1][1],
                  &Bs[s][r][cb]);
        }
#pragma unroll
        for (int i = 0; i < MT; i++)
#pragma unroll
            for (int j = 0; j < NT; j++)
                mma16816(c[i][j], a[i], b[j]);
    };

    const int nIter = kLen / BK;

    load_stage(0, 0);
    asm volatile("cp.async.commit_group;");
    if (1 < nIter) load_stage(1, BK);
    asm volatile("cp.async.commit_group;");
    asm volatile("cp.async.wait_group 1;");
    __syncthreads();

    int s = 0;
    for (int it = 0; it < nIter; it++) {
        compute_half(s, 0);
        {
            int nf = it + 2;
            int sl = s + 2; if (sl >= NSTAGE) sl -= NSTAGE;
            if (nf < nIter) load_stage(sl, nf * BK);
            asm volatile("cp.async.commit_group;");
        }
        compute_half(s, 1);
        asm volatile("cp.async.wait_group 1;");
        __syncthreads();
        s = (s + 1 == NSTAGE) ? 0 : s + 1;
    }

#pragma unroll
    for (int i = 0; i < MT; i++) {
        int row = bm + wm * 64 + i * 16 + (lane >> 2);
#pragma unroll
        for (int j = 0; j < NT; j++) {
            int col = bn + wn * 32 + j * 8 + (lane & 3) * 2;
            if (col < Nc) {
                *(float2*)(Cz + (size_t)row * ldN + col) =
                    make_float2(c[i][j][0], c[i][j][1]);
                *(float2*)(Cz + (size_t)(row + 8) * ldN + col) =
                    make_float2(c[i][j][2], c[i][j][3]);
            }
        }
    }
}

// Split-K reduction
__global__ void addk_kernel(const float* __restrict__ p, float* __restrict__ out,
                            int total4, int ns)
{
    int i = blockIdx.x * blockDim.x + threadIdx.x;
    if (i >= total4) return;
    float4 a = ((const float4*)p)[i];
    for (int s = 1; s < ns; s++) {
        float4 b = ((const float4*)p)[i + (size_t)s * total4];
        a.x += b.x; a.y += b.y; a.z += b.z; a.w += b.w;
    }
    ((float4*)out)[i] = a;
}

// ---------------------------------------------------------------------------
// Causal conv (width 4) + SiLU, fused with bf16 split-pack -> g_xcp
// ---------------------------------------------------------------------------
__global__ void conv_silu_pack(const float* __restrict__ cw,
                               const float* __restrict__ cb)
{
    int i = blockIdx.x * blockDim.x + threadIdx.x;
    const int ngrp = DINNER / 4;
    if (i >= MROWS * ngrp) return;
    int m  = i / ngrp;
    int dg = i % ngrp;
    int l  = m % SEQLEN;
    int d0 = dg * 4;

    float4 acc = make_float4(cb[d0], cb[d0 + 1], cb[d0 + 2], cb[d0 + 3]);
#pragma unroll
    for (int t = 0; t < 4; t++) {
        int li = l - 3 + t;
        if (li >= 0) {
            const float4 v = *(const float4*)&g_xz[(size_t)(m - l + li) * (2 * DINNER) + d0];
            acc.x = fmaf(v.x, __ldg(&cw[(d0 + 0) * 4 + t]), acc.x);
            acc.y = fmaf(v.y, __ldg(&cw[(d0 + 1) * 4 + t]), acc.y);
            acc.z = fmaf(v.z, __ldg(&cw[(d0 + 2) * 4 + t]), acc.z);
            acc.w = fmaf(v.w, __ldg(&cw[(d0 + 3) * 4 + t]), acc.w);
        }
    }
    float f[4];
    f[0] = acc.x / (1.f + expf(-acc.x));
    f[1] = acc.y / (1.f + expf(-acc.y));
    f[2] = acc.z / (1.f + expf(-acc.z));
    f[3] = acc.w / (1.f + expf(-acc.w));

    unsigned long long hs[4], ls[4];
#pragma unroll
    for (int t = 0; t < 4; t++) {
        __nv_bfloat16 h = __float2bfloat16_rn(f[t]);
        __nv_bfloat16 lo = __float2bfloat16_rn(f[t] - __bfloat162float(h));
        hs[t] = (unsigned long long)__bfloat16_as_ushort(h);
        ls[t] = (unsigned long long)__bfloat16_as_ushort(lo);
    }
    unsigned long long hp = hs[0] | (hs[1] << 16) | (hs[2] << 32) | (hs[3] << 48);
    unsigned long long lp = ls[0] | (ls[1] << 16) | (ls[2] << 32) | (ls[3] << 48);
    __nv_bfloat16* base = g_xcp + (size_t)m * KPX + d0;
    *(unsigned long long*)(base)              = hp;
    *(unsigned long long*)(base + DINNER)     = lp;
    *(unsigned long long*)(base + 2 * DINNER) = hp;
}

// ---------------------------------------------------------------------------
// Pre: -> g_pre2 {dt, dt*xc} and g_zw {D*xc*sz, sz}, ch-major, via smem tile.
// Store layout: thread j owns 8 consecutive steps -> float4-packed stores.
// ---------------------------------------------------------------------------
__global__ __launch_bounds__(256) void pre_kernel_tile(
    const float* __restrict__ dt_w, const float* __restrict__ dt_b,
    const float* __restrict__ Dp)
{
    __shared__ float sA[32][65], sB[32][65], sC[32][65], sD[32][65];

    const int NCT = BATCH * DINNER / 32;
    const int tid = threadIdx.x;
    const int tc  = blockIdx.x % NCT;
    const int tl  = blockIdx.x / NCT;
    const int ch0 = tc * 32;
    const int l0  = tl * 64;
    const int b   = ch0 / DINNER;

    const int dof = tid & 31;
    const int d   = (ch0 % DINNER) + dof;
    const int wl  = tid >> 5;

    const float dw = __ldg(dt_w + d), db = __ldg(dt_b + d), Dv = __ldg(Dp + d);

#pragma unroll
    for (int p = 0; p < 8; p++) {
        int le = wl + p * 8;
        int m = b * SEQLEN + l0 + le;
        float dtin = g_xdbl[(size_t)m * XDBL_LD];
        float xarg = fmaf(dtin, dw, db);
        float dt = fmaxf(xarg, 0.f) + log1pf(expf(-fabsf(xarg)));
        float xc = __bfloat162float(g_xcp[(size_t)m * KPX + d]) +
                   __bfloat162float(g_xcp[(size_t)m * KPX + DINNER + d]);
        float z  = g_xz[(size_t)m * (2 * DINNER) + DINNER + d];
        float sz = z / (1.f + expf(-z));
        sA[dof][le] = dt;
        sB[dof][le] = dt * xc;
        sC[dof][le] = Dv * xc * sz;
        sD[dof][le] = sz;
    }
    __syncthreads();

    const int cl = tid >> 3;               // channel within tile
    const int j  = tid & 7;                // 8-step group
    const int e0 = j * 8;
    float4* p2 = (float4*)(g_pre2 + 2 * ((size_t)(ch0 + cl) * SEQLEN + l0 + e0));
    float4* zw = (float4*)(g_zw   + 2 * ((size_t)(ch0 + cl) * SEQLEN + l0 + e0));
#pragma unroll
    for (int k = 0; k < 4; k++) {
        int e = e0 + 2 * k;
        p2[k] = make_float4(sA[cl][e], sB[cl][e], sA[cl][e + 1], sB[cl][e + 1]);
        zw[k] = make_float4(sC[cl][e], sD[cl][e], sC[cl][e + 1], sD[cl][e + 1]);
    }
}

// ---------------------------------------------------------------------------
// Chunked selective scan, 2 channels per warp, NCH=4 chunks of 256.
// Pass 1 (scan_state): pre2 + B only; S and P = exp2(An * sum dt).
// Pass 2 (scan_main): prefix fold, then body; zw loaded by writer lanes only.
// ---------------------------------------------------------------------------
__device__ __forceinline__ float fast_ex2(float x) {
    float r;
    asm("ex2.approx.ftz.f32 %0, %1;" : "=f"(r) : "f"(x));
    return r;
}

__global__ __launch_bounds__(256) void scan_state(const float* __restrict__ A_log)
{
    const int gw   = blockIdx.x * 8 + (threadIdx.x >> 5);
    const int lane = threadIdx.x & 31;
    const int pair  = gw % NPAIR;
    const int chunk = gw / NPAIR;          // 0..NCH-2
    const int b  = pair / (DINNER / 2);
    const int d0 = (pair % (DINNER / 2)) * 2;
    const int chA = b * DINNER + d0;
    const int n0 = 2 * lane;

    const float LOG2E = 1.4426950408889634f;
    const float An0 = -expf(A_log[n0])     * LOG2E;
    const float An1 = -expf(A_log[n0 + 1]) * LOG2E;

    const int l0 = chunk * CHL;
    const float* p2A = g_pre2 + 2 * ((size_t)chA * SEQLEN + l0);
    const float* p2B = p2A + 2 * SEQLEN;
    const float* xb  = g_xdbl + (size_t)(b * SEQLEN + l0) * XDBL_LD;

    float4 qA[2], qB[2]; float2 Bv[4];
#pragma unroll
    for (int k = 0; k < 2; k++) {
        qA[k] = __ldg((const float4*)(p2A + 4 * k));
        qB[k] = __ldg((const float4*)(p2B + 4 * k));
    }
#pragma unroll
    for (int s = 0; s < 4; s++)
        Bv[s] = __ldg((const float2*)(xb + (size_t)s * XDBL_LD + 4 + 2 * n0));

    float hA0 = 0.f, hA1 = 0.f, hB0 = 0.f, hB1 = 0.f;
    float sdA = 0.f, sdB = 0.f;

    for (int l = 0; l < CHL; l += 4) {
#pragma unroll
        for (int s = 0; s < 4; s++) {
            int k = s >> 1;
            float dtA  = (s & 1) ? qA[k].z : qA[k].x;
            float dxA  = (s & 1) ? qA[k].w : qA[k].y;
            float dtB  = (s & 1) ? qB[k].z : qB[k].x;
            float dxB  = (s & 1) ? qB[k].w : qB[k].y;
            float2 c = Bv[s];
            hA0 = fmaf(hA0, fast_ex2(dtA * An0), c.x * dxA);
            hA1 = fmaf(hA1, fast_ex2(dtA * An1), c.y * dxA);
            sdA += dtA;
            hB0 = fmaf(hB0, fast_ex2(dtB * An0), c.x * dxB);
            hB1 = fmaf(hB1, fast_ex2(dtB * An1), c.y * dxB);
            sdB += dtB;
            if (s & 1) {   // finished q[k]; reload for steps l+4+2k, l+5+2k
                int li = l + 4 + 2 * k;
                if (li > CHL - 2) li = CHL - 2;
                qA[k] = __ldg((const float4*)(p2A + 2 * li));
                qB[k] = __ldg((const float4*)(p2B + 2 * li));
            }
            int ln = l + 4 + s;
            if (ln > CHL - 1) ln = CHL - 1;
            Bv[s] = __ldg((const float2*)(xb + (size_t)ln * XDBL_LD + 4 + 2 * n0));
        }
    }

    float2* csA = (float2*)(g_cs + ((size_t)chA * (NCH - 1) + chunk) * 128);
    float2* csB = (float2*)(g_cs + ((size_t)(chA + 1) * (NCH - 1) + chunk) * 128);
    csA[lane]      = make_float2(hA0, hA1);
    csA[32 + lane] = make_float2(fast_ex2(An0 * sdA), fast_ex2(An1 * sdA));
    csB[lane]      = make_float2(hB0, hB1);
    csB[32 + lane] = make_float2(fast_ex2(An0 * sdB), fast_ex2(An1 * sdB));
}

__global__ __launch_bounds__(256) void scan_main(const float* __restrict__ A_log)
{
    const int gw   = blockIdx.x * 8 + (threadIdx.x >> 5);
    const int lane = threadIdx.x & 31;
    const int pair  = gw % NPAIR;
    const int chunk = gw / NPAIR;          // 0..NCH-1
    const int b  = pair / (DINNER / 2);
    const int d0 = (pair % (DINNER / 2)) * 2;
    const int chA = b * DINNER + d0;
    const int n0 = 2 * lane;

    const float LOG2E = 1.4426950408889634f;
    const float An0 = -expf(A_log[n0])     * LOG2E;
    const float An1 = -expf(A_log[n0 + 1]) * LOG2E;

    const int l0 = chunk * CHL;
    const float* p2A = g_pre2 + 2 * ((size_t)chA * SEQLEN + l0);
    const float* p2B = p2A + 2 * SEQLEN;
    const float* xb  = g_xdbl + (size_t)(b * SEQLEN + l0) * XDBL_LD;
    __nv_bfloat16* yoA = g_y2 + (size_t)(b * SEQLEN + l0) * KPX + 3 * d0;
    __nv_bfloat16* yoB = yoA + 3;

    // Writer-lane zw pointer: slot = lane>>2; channel = slot>>2, off = slot&3
    const int slot = lane >> 2;
    const float* zwp = g_zw +
        2 * ((size_t)(chA + (slot >> 2)) * SEQLEN + l0 + (slot & 3));

    // h_in = fold of (h*P + S) over prefix chunks
    float hA0 = 0.f, hA1 = 0.f, hB0 = 0.f, hB1 = 0.f;
    for (int j = 0; j < chunk; j++) {
        const float2* csA = (const float2*)(g_cs + ((size_t)chA * (NCH - 1) + j) * 128);
        const float2* csB = (const float2*)(g_cs + ((size_t)(chA + 1) * (NCH - 1) + j) * 128);
        float2 S = csA[lane], P = csA[32 + lane];
        hA0 = fmaf(hA0, P.x, S.x);
        hA1 = fmaf(hA1, P.y, S.y);
        float2 Sb = csB[lane], Pb = csB[32 + lane];
        hB0 = fmaf(hB0, Pb.x, Sb.x);
        hB1 = fmaf(hB1, Pb.y, Sb.y);
    }

    float4 qA[2], qB[2], bc[4]; float2 zwv;
#pragma unroll
    for (int k = 0; k < 2; k++) {
        qA[k] = __ldg((const float4*)(p2A + 4 * k));
        qB[k] = __ldg((const float4*)(p2B + 4 * k));
    }
#pragma unroll
    for (int s = 0; s < 4; s++)
        bc[s] = __ldg((const float4*)(xb + (size_t)s * XDBL_LD + 4 + 2 * n0));
    zwv = __ldg((const float2*)zwp);

    const bool u16 = (lane & 16) != 0;
    const bool u8  = (lane & 8) != 0;
    const bool u4  = (lane & 4) != 0;

    for (int l = 0; l < CHL; l += 4) {
        float yA[4], yB[4];
#pragma unroll
        for (int s = 0; s < 4; s++) {
            int k = s >> 1;
            float dtA  = (s & 1) ? qA[k].z : qA[k].x;
            float dxA  = (s & 1) ? qA[k].w : qA[k].y;
            float dtB  = (s & 1) ? qB[k].z : qB[k].x;
            float dxB  = (s & 1) ? qB[k].w : qB[k].y;
            float4 c = bc[s];
            hA0 = fmaf(hA0, fast_ex2(dtA * An0), c.x * dxA);
            hA1 = fmaf(hA1, fast_ex2(dtA * An1), c.y * dxA);
            yA[s] = fmaf(hA0, c.z, hA1 * c.w);
            hB0 = fmaf(hB0, fast_ex2(dtB * An0), c.x * dxB);
            hB1 = fmaf(hB1, fast_ex2(dtB * An1), c.y * dxB);
            yB[s] = fmaf(hB0, c.z, hB1 * c.w);
            if (s & 1) {
                int li = l + 4 + 2 * k;
                if (li > CHL - 2) li = CHL - 2;
                qA[k] = __ldg((const float4*)(p2A + 2 * li));
                qB[k] = __ldg((const float4*)(p2B + 2 * li));
            }
            int ln = l + 4 + s;
            if (ln > CHL - 1) ln = CHL - 1;
            bc[s] = __ldg((const float4*)(xb + (size_t)ln * XDBL_LD + 4 + 2 * n0));
        }

        // Split-butterfly reduction: slot s lands in lane 4s (pure y values).
        float v[4];
#pragma unroll
        for (int s = 0; s < 4; s++) {
            float send = u16 ? yA[s] : yB[s];
            float recv = __shfl_xor_sync(0xffffffffu, send, 16);
            v[s] = (u16 ? yB[s] : yA[s]) + recv;
        }
#pragma unroll
        for (int s = 0; s < 2; s++) {
            float send = u8 ? v[s] : v[s + 2];
            float recv = __shfl_xor_sync(0xffffffffu, send, 8);
            v[s] = (u8 ? v[s + 2] : v[s]) + recv;
        }
        {
            float send = u4 ? v[0] : v[1];
            float recv = __shfl_xor_sync(0xffffffffu, send, 4);
            v[0] = (u4 ? v[1] : v[0]) + recv;
        }
        v[0] += __shfl_xor_sync(0xffffffffu, v[0], 2);
        v[0] += __shfl_xor_sync(0xffffffffu, v[0], 1);

        float2 zwc = zwv;
        {   // prefetch next iter's zw (clamped)
            int lz = l + 4;
            if (lz > CHL - 4) lz = CHL - 4;
            zwv = __ldg((const float2*)(zwp + 2 * lz));
        }
        if ((lane & 3) == 0) {
            float yv = fmaf(v[0], zwc.y, zwc.x);
            __nv_bfloat16 hi = __float2bfloat16_rn(yv);
            __nv_bfloat16 lo = __float2bfloat16_rn(yv - __bfloat162float(hi));
            __nv_bfloat16* p = (slot < 4)
                ? yoA + (size_t)(l + slot) * KPX
                : yoB + (size_t)(l + slot - 4) * KPX;
            p[0] = hi; p[1] = lo; p[2] = hi;
        }
    }
}

// ---------------------------------------------------------------------------
extern "C" void kernel_launch(void* const* d_in, const int* in_sizes, int n_in,
                              void* d_out, int out_size)
{
    const float* x      = (const float*)d_in[0];
    const float* W_in   = (const float*)d_in[1];
    const float* conv_w = (const float*)d_in[2];
    const float* conv_b = (const float*)d_in[3];
    const float* W_x    = (const float*)d_in[4];
    const float* dt_w   = (const float*)d_in[5];
    const float* dt_b   = (const float*)d_in[6];
    const float* A_log  = (const float*)d_in[7];
    const float* D_par  = (const float*)d_in[8];
    const float* W_out  = (const float*)d_in[9];
    float* out = (float*)d_out;

    float *p_xz, *p_xdbl, *p_part, *p_pre;
    __nv_bfloat16 *p_xp, *p_wip, *p_xcp, *p_wxp, *p_y2, *p_wop;
    cudaGetSymbolAddress((void**)&p_xz,   g_xz);
    cudaGetSymbolAddress((void**)&p_xdbl, g_xdbl);
    cudaGetSymbolAddress((void**)&p_part, g_xconv);
    cudaGetSymbolAddress((void**)&p_pre,  g_pre);
    cudaGetSymbolAddress((void**)&p_xp,   g_xp);
    cudaGetSymbolAddress((void**)&p_wip,  g_wip);
    cudaGetSymbolAddress((void**)&p_xcp,  g_xcp);
    cudaGetSymbolAddress((void**)&p_wxp,  g_wxp);
    cudaGetSymbolAddress((void**)&p_y2,   g_y2);
    cudaGetSymbolAddress((void**)&p_wop,  g_wop);

    // 1) fused input packs (x, W_in, W_out, W_x)
    pack_all<<<(T_ALL + 255) / 256, 256>>>(x, W_in, W_out, W_x);

    // 2) xz = x @ W_in^T
    gemm_bf16p<<<dim3(2 * DINNER / 128, MROWS / 128, 1), 256>>>(
        p_xp, p_wip, p_xz, MROWS, 2 * DINNER, KP1, KP1, 2 * DINNER);

    // 3) causal conv + silu + pack
    {
        int total = MROWS * (DINNER / 4);
        conv_silu_pack<<<(total + 255) / 256, 256>>>(conv_w, conv_b);
    }

    // 4) x_dbl = x_conv @ W_x~^T (BC-interleaved output cols, splitK=8)
    gemm_bf16p<<<dim3(2, MROWS / 128, 8), 256>>>(
        p_xcp, p_wxp, p_part, MROWS, XDBL_LD, KPX, KPX / 8, XDBL_LD);
    {
        int t4 = MROWS * XDBL_LD / 4;
        addk_kernel<<<(t4 + 255) / 256, 256>>>(p_part, p_xdbl, t4, 8);
    }

    // 5) pre -> g_pre2 / g_zw (channel-major via smem transpose)
    pre_kernel_tile<<<(BATCH * DINNER / 32) * (SEQLEN / 64), 256>>>(
        dt_w, dt_b, D_par);

    // 6) chunked selective scan -> g_y2
    scan_state<<<NPAIR * (NCH - 1) / 8, 256>>>(A_log);
    scan_main<<<NPAIR * NCH / 8, 256>>>(A_log);

    // 7) out = y @ W_out^T (K=4608, splitK=4 in g_pre -> add)
    gemm_bf16p<<<dim3(DMODEL / 128, MROWS / 128, 4), 256>>>(
        p_y2, p_wop, p_pre, MROWS, DMODEL, KPX, KPX / 4, DMODEL);
    {
        int t4 = MROWS * DMODEL / 4;
        addk_kernel<<<(t4 + 255) / 256, 256>>>(p_pre, out, t4, 4);
    }
}